// round 5
// baseline (speedup 1.0000x reference)
#include <cuda_runtime.h>
#include <cuda_bf16.h>
#include <math.h>

// Problem constants (fixed shapes for this problem instance)
#define N_TOK   8192
#define DDIM    4096
#define NE      16
#define KVAL    2

// Logits GEMM tiling
#define KSPLIT  8
#define KRANGE  (DDIM / KSPLIT)   // 512
#define TB      256               // tokens per block tile
#define KC      32                // K chunk
#define XPAD    34                // smem row stride (floats): 17 8B-units -> conflict-free

// Output layout (floats): [ l_aux | token_pos_after(2N) | token_pos_before(2N) | counts(E) | weight(2N) ]
#define OFF_AFTER   1
#define OFF_BEFORE  (1 + 2 * N_TOK)
#define OFF_CNT     (1 + 4 * N_TOK)
#define OFF_W       (1 + 4 * N_TOK + NE)

// Scratch (device globals; no allocations allowed)
__device__ float g_partial[KSPLIT][(size_t)N_TOK * NE];   // 4 MB
__device__ int   g_e1[N_TOK];
__device__ int   g_e2[N_TOK];
__device__ int   g_pos[2 * N_TOK];
__device__ float g_colsum_part[32][NE];

// ---------------------------------------------------------------------------
// Kernel 1: logits partials.  grid = (32 token tiles, 8 K-splits), 128 thr.
// Per-thread micro-tile: 8 tokens x 4 experts, packed f32x2 FMA over K pairs.
// ---------------------------------------------------------------------------
__global__ __launch_bounds__(128) void logits_kernel(
    const float* __restrict__ x, const float* __restrict__ wg)
{
    __shared__ float xs[TB][XPAD];
    __shared__ float ws[NE][XPAD];

    const int tid     = threadIdx.x;
    const int tx      = tid & 3;      // expert group: experts tx*4 .. tx*4+3
    const int ty      = tid >> 2;     // token group: tokens ty + 32*r, r=0..7
    const int tokBase = blockIdx.x * TB;
    const int kBase0  = blockIdx.y * KRANGE;

    unsigned long long acc[32];
#pragma unroll
    for (int i = 0; i < 32; i++) acc[i] = 0ull;  // packed {0.f, 0.f}

    for (int c = 0; c < KRANGE / KC; c++) {
        const int kb = kBase0 + c * KC;

        // Load Wg tile: 16 x 32 floats = 128 float4, one per thread.
        {
            int row = tid >> 3, col = (tid & 7) * 4;
            float4 v = *(const float4*)&wg[(size_t)row * DDIM + kb + col];
            *(float2*)&ws[row][col]     = make_float2(v.x, v.y);
            *(float2*)&ws[row][col + 2] = make_float2(v.z, v.w);
        }
        // Load x tile: 256 x 32 floats = 2048 float4, 16 per thread.
#pragma unroll
        for (int p = 0; p < 16; p++) {
            int idx = tid + p * 128;
            int row = idx >> 3, col = (idx & 7) * 4;
            float4 v = *(const float4*)&x[(size_t)(tokBase + row) * DDIM + kb + col];
            *(float2*)&xs[row][col]     = make_float2(v.x, v.y);
            *(float2*)&xs[row][col + 2] = make_float2(v.z, v.w);
        }
        __syncthreads();

#pragma unroll
        for (int kk = 0; kk < KC / 2; kk++) {
            unsigned long long w2[4], x2[8];
#pragma unroll
            for (int j = 0; j < 4; j++)
                w2[j] = *(const unsigned long long*)&ws[tx * 4 + j][kk * 2];
#pragma unroll
            for (int r = 0; r < 8; r++)
                x2[r] = *(const unsigned long long*)&xs[ty + r * 32][kk * 2];
#pragma unroll
            for (int r = 0; r < 8; r++)
#pragma unroll
                for (int j = 0; j < 4; j++)
                    asm("fma.rn.f32x2 %0, %1, %2, %0;"
                        : "+l"(acc[r * 4 + j]) : "l"(x2[r]), "l"(w2[j]));
        }
        __syncthreads();
    }

    // Write partials: float4 per (token, 4 experts)
#pragma unroll
    for (int r = 0; r < 8; r++) {
        float4 v;
        float* vp = (float*)&v;
#pragma unroll
        for (int j = 0; j < 4; j++) {
            unsigned long long a = acc[r * 4 + j];
            float lo = __uint_as_float((unsigned)(a & 0xffffffffull));
            float hi = __uint_as_float((unsigned)(a >> 32));
            vp[j] = lo + hi;
        }
        int tok = tokBase + ty + r * 32;
        *(float4*)&g_partial[blockIdx.y][(size_t)tok * NE + tx * 4] = v;
    }
}

// ---------------------------------------------------------------------------
// Kernel 2: reduce partials, softmax, top-2, weights, per-block gate colsums.
// One thread per token.  grid = 32 x 256.
// ---------------------------------------------------------------------------
__global__ __launch_bounds__(256) void gate_kernel(float* __restrict__ out_w)
{
    __shared__ float warp_sums[8][NE];

    const int t = blockIdx.x * 256 + threadIdx.x;

    float l[NE];
#pragma unroll
    for (int e = 0; e < NE; e++) l[e] = 0.0f;
#pragma unroll
    for (int s = 0; s < KSPLIT; s++) {
#pragma unroll
        for (int q = 0; q < 4; q++) {
            float4 v = *(const float4*)&g_partial[s][(size_t)t * NE + q * 4];
            l[q * 4 + 0] += v.x; l[q * 4 + 1] += v.y;
            l[q * 4 + 2] += v.z; l[q * 4 + 3] += v.w;
        }
    }

    // softmax
    float m = l[0];
#pragma unroll
    for (int e = 1; e < NE; e++) m = fmaxf(m, l[e]);
    float p[NE], sum = 0.0f;
#pragma unroll
    for (int e = 0; e < NE; e++) { p[e] = expf(l[e] - m); sum += p[e]; }

    // top-2 (ties -> lowest index, matching lax.top_k)
    int e1 = 0; float b1 = l[0];
#pragma unroll
    for (int e = 1; e < NE; e++) if (l[e] > b1) { b1 = l[e]; e1 = e; }
    int e2 = -1; float b2 = -3.4e38f;
#pragma unroll
    for (int e = 0; e < NE; e++) if (e != e1 && l[e] > b2) { b2 = l[e]; e2 = e; }

    float p1 = p[e1], p2 = p[e2];
    float invn = 1.0f / (p1 + p2);
    out_w[t]         = p1 * invn;
    out_w[N_TOK + t] = p2 * invn;
    g_e1[t] = e1;
    g_e2[t] = e2;

    // deterministic per-block gate column sums (for me)
    float invs = 1.0f / sum;
#pragma unroll
    for (int e = 0; e < NE; e++) {
        float g = p[e] * invs;
#pragma unroll
        for (int off = 16; off > 0; off >>= 1)
            g += __shfl_xor_sync(0xffffffffu, g, off);
        if ((threadIdx.x & 31) == 0) warp_sums[threadIdx.x >> 5][e] = g;
    }
    __syncthreads();
    if (threadIdx.x < NE) {
        float s2 = 0.0f;
        for (int w = 0; w < 8; w++) s2 += warp_sums[w][threadIdx.x];
        g_colsum_part[blockIdx.x][threadIdx.x] = s2;
    }
}

// ---------------------------------------------------------------------------
// Kernel 3: order-preserving per-expert ranking, offsets, scatter, l_aux.
// Single block of 512 threads, 32 batches in sequence-order.
// ---------------------------------------------------------------------------
__global__ __launch_bounds__(512) void rank_kernel(float* __restrict__ out)
{
    __shared__ int hist[16][NE];    // [warp][expert]
    __shared__ int pre[16][NE];
    __shared__ int running[NE];
    __shared__ int top1cnt[NE];
    __shared__ int offs[NE];
    __shared__ int cnt[NE];

    const int tid  = threadIdx.x;
    const int lane = tid & 31;
    const int warp = tid >> 5;

    if (tid < NE) running[tid] = 0;
    __syncthreads();

    for (int b = 0; b < 32; b++) {
        const int i = b * 512 + tid;
        const int e = (i < N_TOK) ? g_e1[i] : g_e2[i - N_TOK];

        if (tid < 256) ((int*)hist)[tid] = 0;
        __syncthreads();

        unsigned mask = __match_any_sync(0xffffffffu, e);
        int lr = __popc(mask & ((1u << lane) - 1u));
        if ((__ffs(mask) - 1) == lane) hist[warp][e] = __popc(mask);
        __syncthreads();

        if (tid < NE) {
            int r = running[tid];
            for (int w = 0; w < 16; w++) { pre[w][tid] = r; r += hist[w][tid]; }
            running[tid] = r;
            if (b == 15) top1cnt[tid] = r;   // counts over i < N only (top-1 mask)
        }
        __syncthreads();

        g_pos[i] = pre[warp][e] + lr;
    }

    if (tid < NE) cnt[tid] = running[tid];
    __syncthreads();
    if (tid == 0) {
        int o = 0;
        for (int e = 0; e < NE; e++) { offs[e] = o; o += cnt[e]; }
    }
    __syncthreads();

    for (int b = 0; b < 32; b++) {
        const int i = b * 512 + tid;
        const int e = (i < N_TOK) ? g_e1[i] : g_e2[i - N_TOK];
        const int after = g_pos[i] + offs[e];
        out[OFF_AFTER + i]       = (float)after;
        out[OFF_BEFORE + after]  = (float)i;   // permutation -> fills all slots
    }

    if (tid < NE) out[OFF_CNT + tid] = (float)cnt[tid];

    if (tid == 0) {
        float l = 0.0f;
        for (int e = 0; e < NE; e++) {
            float me = 0.0f;
            for (int blk = 0; blk < 32; blk++) me += g_colsum_part[blk][e];
            me /= (float)N_TOK;
            float ce = (float)top1cnt[e] / (float)N_TOK;
            l += me * ce;
        }
        out[0] = l * (float)NE;
    }
}

// ---------------------------------------------------------------------------
extern "C" void kernel_launch(void* const* d_in, const int* in_sizes, int n_in,
                              void* d_out, int out_size)
{
    const float* x  = (const float*)d_in[0];   // [8192, 4096] f32
    const float* wg = (const float*)d_in[1];   // [16, 4096] f32
    float* out = (float*)d_out;

    dim3 lgrid(N_TOK / TB, KSPLIT);            // (32, 8)
    logits_kernel<<<lgrid, 128>>>(x, wg);
    gate_kernel<<<N_TOK / 256, 256>>>(out + OFF_W);
    rank_kernel<<<1, 512>>>(out);
}

// round 8
// speedup vs baseline: 1.5705x; 1.5705x over previous
#include <cuda_runtime.h>
#include <cuda_bf16.h>
#include <math.h>

// Problem constants
#define N_TOK   8192
#define DDIM    4096
#define NE      16

// Logits GEMM tiling
#define KSPLIT  16
#define KRANGE  (DDIM / KSPLIT)   // 256
#define KC      16                // K per pipeline stage
#define NITER   (KRANGE / KC)     // 16
#define TB      256               // tokens per block tile
#define XP      20                // smem row stride (floats): 80B, 16B-aligned, conflict-free

// Output layout (floats): [ l_aux | token_pos_after(2N) | token_pos_before(2N) | counts(E) | weight(2N) ]
#define OFF_AFTER   1
#define OFF_BEFORE  (1 + 2 * N_TOK)
#define OFF_CNT     (1 + 4 * N_TOK)
#define OFF_W       (1 + 4 * N_TOK + NE)

#define NBLK 32   // gate/scatter token blocks of 256

// Scratch (device globals; no allocations allowed)
__device__ float g_partial[KSPLIT][(size_t)N_TOK * NE];   // 8 MB
__device__ int   g_info[N_TOK];          // packed e1|r1|e2|r2
__device__ int   g_h1[NBLK][NE];
__device__ int   g_h2[NBLK][NE];
__device__ int   g_base1[NBLK][NE];
__device__ int   g_base2[NBLK][NE];
__device__ int   g_offs[NE];
__device__ float g_colsum_part[NBLK][NE];

__device__ __forceinline__ void cpa16(void* dst, const void* src) {
    unsigned d = (unsigned)__cvta_generic_to_shared(dst);
    asm volatile("cp.async.cg.shared.global [%0], [%1], 16;" :: "r"(d), "l"(src));
}

// ---------------------------------------------------------------------------
// Kernel 1: logits partials.  grid = (32 token tiles, 16 K-splits), 128 thr.
// 2-stage cp.async pipeline; per-thread micro-tile 8 tokens x 4 experts (f32x2).
// ---------------------------------------------------------------------------
__global__ __launch_bounds__(128) void logits_kernel(
    const float* __restrict__ x, const float* __restrict__ wg)
{
    __shared__ float xs[2][TB][XP];   // 2*256*20*4 = 40960 B
    __shared__ float ws[2][NE][XP];   // 2*16*20*4  =  2560 B

    const int tid     = threadIdx.x;
    const int tx      = tid & 3;      // expert group: experts tx*4 .. tx*4+3
    const int ty      = tid >> 2;     // token group: tokens ty + 32*r, r=0..7
    const int tokBase = blockIdx.x * TB;
    const int kBase0  = blockIdx.y * KRANGE;

    auto load_stage = [&](int c, int buf) {
        const int kb = kBase0 + c * KC;
#pragma unroll
        for (int p = 0; p < 8; p++) {
            int id  = tid + p * 128;
            int row = id >> 2, col = (id & 3) * 4;
            cpa16(&xs[buf][row][col], &x[(size_t)(tokBase + row) * DDIM + kb + col]);
        }
        if (tid < 64) {
            int row = tid >> 2, col = (tid & 3) * 4;
            cpa16(&ws[buf][row][col], &wg[(size_t)row * DDIM + kb + col]);
        }
        asm volatile("cp.async.commit_group;");
    };

    unsigned long long acc[32];
#pragma unroll
    for (int i = 0; i < 32; i++) acc[i] = 0ull;   // packed {0.f, 0.f}

    load_stage(0, 0);

    for (int c = 0; c < NITER; c++) {
        const int buf = c & 1;
        if (c + 1 < NITER) {
            load_stage(c + 1, buf ^ 1);
            asm volatile("cp.async.wait_group 1;");   // stage c complete
        } else {
            asm volatile("cp.async.wait_group 0;");
        }
        __syncthreads();

#pragma unroll
        for (int kk = 0; kk < KC / 2; kk++) {
            unsigned long long w2[4], x2[8];
#pragma unroll
            for (int j = 0; j < 4; j++)
                w2[j] = *(const unsigned long long*)&ws[buf][tx * 4 + j][kk * 2];
#pragma unroll
            for (int r = 0; r < 8; r++)
                x2[r] = *(const unsigned long long*)&xs[buf][ty + r * 32][kk * 2];
#pragma unroll
            for (int r = 0; r < 8; r++)
#pragma unroll
                for (int j = 0; j < 4; j++)
                    asm("fma.rn.f32x2 %0, %1, %2, %0;"
                        : "+l"(acc[r * 4 + j]) : "l"(x2[r]), "l"(w2[j]));
        }
        __syncthreads();   // all reads of buf done before stage c+2 overwrites it
    }

    // Write partials: float4 per (token, 4 experts)
#pragma unroll
    for (int r = 0; r < 8; r++) {
        float4 v;
        float* vp = (float*)&v;
#pragma unroll
        for (int j = 0; j < 4; j++) {
            unsigned long long a = acc[r * 4 + j];
            float lo = __uint_as_float((unsigned)(a & 0xffffffffull));
            float hi = __uint_as_float((unsigned)(a >> 32));
            vp[j] = lo + hi;
        }
        int tok = tokBase + ty + r * 32;
        *(float4*)&g_partial[blockIdx.y][(size_t)tok * NE + tx * 4] = v;
    }
}

// ---------------------------------------------------------------------------
// Kernel 2: reduce partials, softmax, top-2, weights, per-block histograms
// and within-block per-expert ranks.  grid = 32 x 256 (one thread per token).
// ---------------------------------------------------------------------------
__global__ __launch_bounds__(256) void gate_kernel(float* __restrict__ out_w)
{
    __shared__ int   wh1[8][NE], wh2[8][NE];
    __shared__ int   pre1[8][NE], pre2[8][NE];
    __shared__ float warp_sums[8][NE];

    const int tid  = threadIdx.x;
    const int lane = tid & 31;
    const int warp = tid >> 5;
    const int t    = blockIdx.x * 256 + tid;

    float l[NE];
#pragma unroll
    for (int e = 0; e < NE; e++) l[e] = 0.0f;
#pragma unroll
    for (int s = 0; s < KSPLIT; s++) {
#pragma unroll
        for (int q = 0; q < 4; q++) {
            float4 v = *(const float4*)&g_partial[s][(size_t)t * NE + q * 4];
            l[q * 4 + 0] += v.x; l[q * 4 + 1] += v.y;
            l[q * 4 + 2] += v.z; l[q * 4 + 3] += v.w;
        }
    }

    // softmax
    float m = l[0];
#pragma unroll
    for (int e = 1; e < NE; e++) m = fmaxf(m, l[e]);
    float p[NE], sum = 0.0f;
#pragma unroll
    for (int e = 0; e < NE; e++) { p[e] = expf(l[e] - m); sum += p[e]; }

    // top-2 (strict > keeps lowest index, matching lax.top_k tie behavior)
    int e1 = 0; float b1 = l[0];
#pragma unroll
    for (int e = 1; e < NE; e++) if (l[e] > b1) { b1 = l[e]; e1 = e; }
    int e2 = -1; float b2 = -3.4e38f;
#pragma unroll
    for (int e = 0; e < NE; e++) if (e != e1 && l[e] > b2) { b2 = l[e]; e2 = e; }

    float p1 = p[e1], p2 = p[e2];
    float invn = 1.0f / (p1 + p2);
    out_w[t]         = p1 * invn;
    out_w[N_TOK + t] = p2 * invn;

    // per-warp expert histograms + lane ranks (order-preserving within warp)
    if (tid < 128) { ((int*)wh1)[tid] = 0; ((int*)wh2)[tid] = 0; }
    __syncthreads();

    unsigned m1  = __match_any_sync(0xffffffffu, e1);
    int      lr1 = __popc(m1 & ((1u << lane) - 1u));
    if ((__ffs(m1) - 1) == lane) wh1[warp][e1] = __popc(m1);
    unsigned m2  = __match_any_sync(0xffffffffu, e2);
    int      lr2 = __popc(m2 & ((1u << lane) - 1u));
    if ((__ffs(m2) - 1) == lane) wh2[warp][e2] = __popc(m2);
    __syncthreads();

    if (tid < NE) {
        int r = 0;
#pragma unroll
        for (int w = 0; w < 8; w++) { pre1[w][tid] = r; r += wh1[w][tid]; }
        g_h1[blockIdx.x][tid] = r;
        r = 0;
#pragma unroll
        for (int w = 0; w < 8; w++) { pre2[w][tid] = r; r += wh2[w][tid]; }
        g_h2[blockIdx.x][tid] = r;
    }
    __syncthreads();

    const int r1 = pre1[warp][e1] + lr1;   // < 256
    const int r2 = pre2[warp][e2] + lr2;   // < 256
    g_info[t] = e1 | (r1 << 4) | (e2 << 12) | (r2 << 16);

    // deterministic per-block gate column sums (for me / l_aux)
    float invs = 1.0f / sum;
#pragma unroll
    for (int e = 0; e < NE; e++) {
        float g = p[e] * invs;
#pragma unroll
        for (int off = 16; off > 0; off >>= 1)
            g += __shfl_xor_sync(0xffffffffu, g, off);
        if (lane == 0) warp_sums[warp][e] = g;
    }
    __syncthreads();
    if (tid < NE) {
        float s2 = 0.0f;
#pragma unroll
        for (int w = 0; w < 8; w++) s2 += warp_sums[w][tid];
        g_colsum_part[blockIdx.x][tid] = s2;
    }
}

// ---------------------------------------------------------------------------
// Kernel 3: tiny scan — block-histogram prefixes, expert offsets, counts, l_aux.
// 1 block, 32 threads.
// ---------------------------------------------------------------------------
__global__ void scan_kernel(float* __restrict__ out)
{
    __shared__ int cnt1[NE], tot[NE];
    const int e = threadIdx.x;
    if (e < NE) {
        int s = 0;
#pragma unroll
        for (int b = 0; b < NBLK; b++) { g_base1[b][e] = s; s += g_h1[b][e]; }
        cnt1[e] = s;                      // top-1 counts (ce numerator)
#pragma unroll
        for (int b = 0; b < NBLK; b++) { g_base2[b][e] = s; s += g_h2[b][e]; }
        tot[e] = s;
        out[OFF_CNT + e] = (float)s;
    }
    __syncthreads();
    if (e == 0) {
        int o = 0;
        for (int q = 0; q < NE; q++) { g_offs[q] = o; o += tot[q]; }
        float laux = 0.0f;
        for (int q = 0; q < NE; q++) {
            float me = 0.0f;
#pragma unroll
            for (int b = 0; b < NBLK; b++) me += g_colsum_part[b][q];
            me /= (float)N_TOK;
            laux += me * ((float)cnt1[q] / (float)N_TOK);
        }
        out[0] = laux * (float)NE;
    }
}

// ---------------------------------------------------------------------------
// Kernel 4: scatter — token_pos_after / token_pos_before.  grid = 32 x 256.
// ---------------------------------------------------------------------------
__global__ __launch_bounds__(256) void scatter_kernel(float* __restrict__ out)
{
    __shared__ int sb1[NE], sb2[NE];
    const int b   = blockIdx.x;
    const int tid = threadIdx.x;
    if (tid < NE) {
        int o = g_offs[tid];
        sb1[tid] = g_base1[b][tid] + o;
        sb2[tid] = g_base2[b][tid] + o;
    }
    __syncthreads();

    const int t    = b * 256 + tid;
    const int info = g_info[t];
    const int e1 = info & 15, r1 = (info >> 4) & 255;
    const int e2 = (info >> 12) & 15, r2 = (info >> 16) & 255;
    const int a1 = sb1[e1] + r1;
    const int a2 = sb2[e2] + r2;

    out[OFF_AFTER + t]          = (float)a1;
    out[OFF_AFTER + N_TOK + t]  = (float)a2;
    out[OFF_BEFORE + a1]        = (float)t;           // permutation -> fills all
    out[OFF_BEFORE + a2]        = (float)(N_TOK + t);
}

// ---------------------------------------------------------------------------
extern "C" void kernel_launch(void* const* d_in, const int* in_sizes, int n_in,
                              void* d_out, int out_size)
{
    const float* x  = (const float*)d_in[0];   // [8192, 4096] f32
    const float* wg = (const float*)d_in[1];   // [16, 4096] f32
    float* out = (float*)d_out;

    dim3 lgrid(N_TOK / TB, KSPLIT);            // (32, 16)
    logits_kernel<<<lgrid, 128>>>(x, wg);
    gate_kernel<<<NBLK, 256>>>(out + OFF_W);
    scan_kernel<<<1, 32>>>(out);
    scatter_kernel<<<NBLK, 256>>>(out);
}

// round 10
// speedup vs baseline: 1.7813x; 1.1342x over previous
#include <cuda_runtime.h>
#include <cuda_bf16.h>
#include <math.h>

// Problem constants
#define N_TOK   8192
#define DDIM    4096
#define NE      16

// Logits GEMM tiling
#define KSPLIT  16
#define KRANGE  (DDIM / KSPLIT)   // 256
#define KC      16                // K per pipeline stage
#define NITER   (KRANGE / KC)     // 16
#define TB      256               // tokens per block tile
#define XP      20                // smem row stride (floats): 80B, conflict-free

// Output layout (floats): [ l_aux | token_pos_after(2N) | token_pos_before(2N) | counts(E) | weight(2N) ]
#define OFF_AFTER   1
#define OFF_BEFORE  (1 + 2 * N_TOK)
#define OFF_CNT     (1 + 4 * N_TOK)
#define OFF_W       (1 + 4 * N_TOK + NE)

#define NBLK 32   // gate blocks of 256 tokens

// Scratch (device globals; no allocations allowed)
__device__ float    g_partial[KSPLIT][(size_t)N_TOK * NE];   // 8 MB
__device__ int      g_h1[NBLK][NE];
__device__ int      g_h2[NBLK][NE];
__device__ float    g_colsum_part[NBLK][NE];
__device__ unsigned g_bar;   // ticket barrier counter (never reset; epoch math)

__device__ __forceinline__ void cpa16(void* dst, const void* src) {
    unsigned d = (unsigned)__cvta_generic_to_shared(dst);
    asm volatile("cp.async.cg.shared.global [%0], [%1], 16;" :: "r"(d), "l"(src));
}

// ---------------------------------------------------------------------------
// Kernel 1: logits partials.  grid = (32 token tiles, 16 K-splits), 128 thr.
// 2-buffer cp.async pipeline, ONE barrier per iteration.
// Per-thread micro-tile: 8 tokens x 4 experts, packed f32x2 FMA.
// ---------------------------------------------------------------------------
__global__ __launch_bounds__(128) void logits_kernel(
    const float* __restrict__ x, const float* __restrict__ wg)
{
    __shared__ float xs[2][TB][XP];   // 40960 B
    __shared__ float ws[2][NE][XP];   //  2560 B

    const int tid     = threadIdx.x;
    const int tx      = tid & 3;      // expert group: experts tx*4 .. tx*4+3
    const int ty      = tid >> 2;     // token group: tokens ty + 32*r
    const int tokBase = blockIdx.x * TB;
    const int kBase0  = blockIdx.y * KRANGE;

    auto load_stage = [&](int c, int buf) {
        const int kb = kBase0 + c * KC;
#pragma unroll
        for (int p = 0; p < 8; p++) {
            int id  = tid + p * 128;
            int row = id >> 2, col = (id & 3) * 4;
            cpa16(&xs[buf][row][col], &x[(size_t)(tokBase + row) * DDIM + kb + col]);
        }
        if (tid < 64) {
            int row = tid >> 2, col = (tid & 3) * 4;
            cpa16(&ws[buf][row][col], &wg[(size_t)row * DDIM + kb + col]);
        }
        asm volatile("cp.async.commit_group;");
    };

    unsigned long long acc[32];
#pragma unroll
    for (int i = 0; i < 32; i++) acc[i] = 0ull;   // packed {0.f, 0.f}

    load_stage(0, 0);

    for (int c = 0; c < NITER; c++) {
        const int buf = c & 1;
        asm volatile("cp.async.wait_group 0;");
        __syncthreads();   // (a) publish all threads' stage-c data
                           // (b) all iter c-1 reads done -> safe to overwrite buf^1
        if (c + 1 < NITER) load_stage(c + 1, buf ^ 1);

#pragma unroll
        for (int kk = 0; kk < KC / 2; kk++) {
            unsigned long long w2[4], x2[8];
#pragma unroll
            for (int j = 0; j < 4; j++)
                w2[j] = *(const unsigned long long*)&ws[buf][tx * 4 + j][kk * 2];
#pragma unroll
            for (int r = 0; r < 8; r++)
                x2[r] = *(const unsigned long long*)&xs[buf][ty + r * 32][kk * 2];
#pragma unroll
            for (int r = 0; r < 8; r++)
#pragma unroll
                for (int j = 0; j < 4; j++)
                    asm("fma.rn.f32x2 %0, %1, %2, %0;"
                        : "+l"(acc[r * 4 + j]) : "l"(x2[r]), "l"(w2[j]));
        }
    }

    // Write partials: float4 per (token, 4 experts)
#pragma unroll
    for (int r = 0; r < 8; r++) {
        float4 v;
        float* vp = (float*)&v;
#pragma unroll
        for (int j = 0; j < 4; j++) {
            unsigned long long a = acc[r * 4 + j];
            float lo = __uint_as_float((unsigned)(a & 0xffffffffull));
            float hi = __uint_as_float((unsigned)(a >> 32));
            vp[j] = lo + hi;
        }
        int tok = tokBase + ty + r * 32;
        *(float4*)&g_partial[blockIdx.y][(size_t)tok * NE + tx * 4] = v;
    }
}

// ---------------------------------------------------------------------------
// Kernel 2 (fused): reduce + softmax + top-2 + weights + ranks, grid barrier,
// scan + offsets + counts + l_aux + scatter.  grid = 32 x 256.
// Grid barrier is safe: 32 blocks < 148 SMs -> always co-resident.
// Ticket scheme is graph-replay safe: each launch consumes exactly NBLK
// tickets; target = ticket - ticket%NBLK + NBLK (2^32 % NBLK == 0).
// ---------------------------------------------------------------------------
__global__ __launch_bounds__(256) void gate_fused_kernel(float* __restrict__ out)
{
    __shared__ int   wh1[8][NE], wh2[8][NE];
    __shared__ int   pre1[8][NE], pre2[8][NE];
    __shared__ float warp_sums[8][NE];
    __shared__ int   sb1[NE], sb2[NE], tot_s[NE], cnt1_s[NE];

    const int tid  = threadIdx.x;
    const int lane = tid & 31;
    const int warp = tid >> 5;
    const int blk  = blockIdx.x;
    const int t    = blk * 256 + tid;

    // ---- Phase A: logits reduce, softmax, top-2 ----
    float l[NE];
#pragma unroll
    for (int e = 0; e < NE; e++) l[e] = 0.0f;
#pragma unroll
    for (int s = 0; s < KSPLIT; s++) {
#pragma unroll
        for (int q = 0; q < 4; q++) {
            float4 v = *(const float4*)&g_partial[s][(size_t)t * NE + q * 4];
            l[q * 4 + 0] += v.x; l[q * 4 + 1] += v.y;
            l[q * 4 + 2] += v.z; l[q * 4 + 3] += v.w;
        }
    }

    float m = l[0];
#pragma unroll
    for (int e = 1; e < NE; e++) m = fmaxf(m, l[e]);
    float p[NE], sum = 0.0f;
#pragma unroll
    for (int e = 0; e < NE; e++) { p[e] = expf(l[e] - m); sum += p[e]; }

    // top-2 (strict > keeps lowest index, matching lax.top_k ties)
    int e1 = 0; float b1 = l[0];
#pragma unroll
    for (int e = 1; e < NE; e++) if (l[e] > b1) { b1 = l[e]; e1 = e; }
    int e2 = -1; float b2 = -3.4e38f;
#pragma unroll
    for (int e = 0; e < NE; e++) if (e != e1 && l[e] > b2) { b2 = l[e]; e2 = e; }

    float p1 = p[e1], p2 = p[e2];
    float invn = 1.0f / (p1 + p2);
    out[OFF_W + t]         = p1 * invn;
    out[OFF_W + N_TOK + t] = p2 * invn;

    // per-warp expert histograms + in-warp ranks (order-preserving)
    if (tid < 128) { ((int*)wh1)[tid] = 0; ((int*)wh2)[tid] = 0; }
    __syncthreads();

    unsigned m1  = __match_any_sync(0xffffffffu, e1);
    int      lr1 = __popc(m1 & ((1u << lane) - 1u));
    if ((__ffs(m1) - 1) == lane) wh1[warp][e1] = __popc(m1);
    unsigned m2  = __match_any_sync(0xffffffffu, e2);
    int      lr2 = __popc(m2 & ((1u << lane) - 1u));
    if ((__ffs(m2) - 1) == lane) wh2[warp][e2] = __popc(m2);
    __syncthreads();

    if (tid < NE) {
        int r = 0;
#pragma unroll
        for (int w = 0; w < 8; w++) { pre1[w][tid] = r; r += wh1[w][tid]; }
        g_h1[blk][tid] = r;
        r = 0;
#pragma unroll
        for (int w = 0; w < 8; w++) { pre2[w][tid] = r; r += wh2[w][tid]; }
        g_h2[blk][tid] = r;
    }
    __syncthreads();

    const int r1 = pre1[warp][e1] + lr1;   // in-block rank, < 256
    const int r2 = pre2[warp][e2] + lr2;

    // deterministic per-block gate column sums (for l_aux's me)
    float invs = 1.0f / sum;
#pragma unroll
    for (int e = 0; e < NE; e++) {
        float g = p[e] * invs;
#pragma unroll
        for (int off = 16; off > 0; off >>= 1)
            g += __shfl_xor_sync(0xffffffffu, g, off);
        if (lane == 0) warp_sums[warp][e] = g;
    }
    __syncthreads();
    if (tid < NE) {
        float s2 = 0.0f;
#pragma unroll
        for (int w = 0; w < 8; w++) s2 += warp_sums[w][tid];
        g_colsum_part[blk][tid] = s2;
    }

    // ---- Grid barrier (ticket-based, replay-safe) ----
    __threadfence();     // publish g_h1/g_h2/g_colsum_part
    __syncthreads();     // all threads' stores precede the arrive
    if (tid == 0) {
        unsigned ticket = atomicAdd(&g_bar, 1u);
        unsigned target = ticket - (ticket % NBLK) + NBLK;
        while (atomicAdd(&g_bar, 0u) < target) __nanosleep(64);
    }
    __syncthreads();
    __threadfence();     // acquire: make all blocks' stores visible

    // ---- Phase B: decomposed scan (every block computes it; tiny) ----
    if (tid < NE) {
        const int e = tid;
        int s = 0, my1 = 0, my2 = 0;
#pragma unroll
        for (int bb = 0; bb < NBLK; bb++) { if (bb == blk) my1 = s; s += g_h1[bb][e]; }
        cnt1_s[e] = s;                         // top-1 counts (ce numerator)
#pragma unroll
        for (int bb = 0; bb < NBLK; bb++) { if (bb == blk) my2 = s; s += g_h2[bb][e]; }
        tot_s[e] = s;
        sb1[e] = my1; sb2[e] = my2;
    }
    __syncthreads();
    if (tid < NE) {
        int o = 0;
        for (int q = 0; q < tid; q++) o += tot_s[q];   // exclusive expert offset
        sb1[tid] += o; sb2[tid] += o;
        if (blk == 0) out[OFF_CNT + tid] = (float)tot_s[tid];
    }
    __syncthreads();

    // ---- Scatter (e/r kept in registers across the barrier) ----
    const int a1 = sb1[e1] + r1;
    const int a2 = sb2[e2] + r2;
    out[OFF_AFTER + t]         = (float)a1;
    out[OFF_AFTER + N_TOK + t] = (float)a2;
    out[OFF_BEFORE + a1]       = (float)t;            // permutation -> fills all
    out[OFF_BEFORE + a2]       = (float)(N_TOK + t);

    // ---- l_aux (block 0 only) ----
    if (blk == 0 && tid == 0) {
        float laux = 0.0f;
        for (int q = 0; q < NE; q++) {
            float me = 0.0f;
#pragma unroll
            for (int bb = 0; bb < NBLK; bb++) me += g_colsum_part[bb][q];
            me /= (float)N_TOK;
            laux += me * ((float)cnt1_s[q] / (float)N_TOK);
        }
        out[0] = laux * (float)NE;
    }
}

// ---------------------------------------------------------------------------
extern "C" void kernel_launch(void* const* d_in, const int* in_sizes, int n_in,
                              void* d_out, int out_size)
{
    const float* x  = (const float*)d_in[0];   // [8192, 4096] f32
    const float* wg = (const float*)d_in[1];   // [16, 4096] f32
    float* out = (float*)d_out;

    dim3 lgrid(N_TOK / TB, KSPLIT);            // (32, 16)
    logits_kernel<<<lgrid, 128>>>(x, wg);
    gate_fused_kernel<<<NBLK, 256>>>(out);
}